// round 1
// baseline (speedup 1.0000x reference)
#include <cuda_runtime.h>

// Shapes (fixed by the problem):
//   p1: [6,256,256] f32   bank
//   p2: [131072,256] f32  table
//   p3: [6,1] i32         row ids into p2
//   p4: [1,256] i32       gather columns
//   p5: [6,1] i32         slot (c index) per batch
//   p6: [1,256] i32       scatter columns
//   p7: [6,256,256] f32   EMA state
//   p8: [12,6,256] f32    query features
// out1: [12,6,256] f32, out2: [6,256,256] f32 (concatenated in d_out)

#define B 6
#define S 256
#define D 256
#define A 12

// Scratch: substituted row (the bank row at c==slot after the scatter), per batch.
__device__ float g_row_scratch[B * D];

// Pre-kernel: build the scattered row. One block per b.
// row = p1[b, slot_b, :]; then row[p6[d]] = p2[p3[b], p4[d]].
__global__ void prep_kernel(const float* __restrict__ p1,
                            const float* __restrict__ p2,
                            const int* __restrict__ p3,
                            const int* __restrict__ p4,
                            const int* __restrict__ p5,
                            const int* __restrict__ p6) {
    int b = blockIdx.x;
    int t = threadIdx.x;              // 0..255 = d
    int slot = p5[b];
    g_row_scratch[b * D + t] = p1[(b * S + slot) * D + t];
    __syncthreads();
    int row = p3[b];
    float g = p2[(long long)row * D + p4[t]];
    g_row_scratch[b * D + p6[t]] = g;
}

// Fused kernel: grid = (D/32 d-tiles, B). 256 threads: tx = d lane (0..31),
// ty = c group (0..7). Each block covers all 256 c for one (b, 32-d) strip:
//   - add = (c==slot ? scattered row : p1) + 0.975*p7
//   - out2[b,d,c] = add[b,c,d]   (smem transpose, coalesced both sides)
//   - out1[a,b,d] = sum_c p8[a,b,c]*add[b,c,d]  (complete in-block, no atomics)
__global__ __launch_bounds__(256)
void fused_kernel(const float* __restrict__ p1,
                  const float* __restrict__ p7,
                  const float* __restrict__ p8,
                  const int* __restrict__ p5,
                  float* __restrict__ out1,
                  float* __restrict__ out2) {
    __shared__ float p8s[A * 256];      // 12 KB: p8[a, b, c] for this b
    __shared__ float s[32 * 33];        // transpose tile, padded
    __shared__ float g[32];             // scattered-row slice for this d tile
    __shared__ float red[8 * A * 32];   // 12 KB: cross-ty reduction

    const int b  = blockIdx.y;
    const int d0 = blockIdx.x * 32;
    const int t  = threadIdx.x;
    const int tx = t & 31;
    const int ty = t >> 5;
    const int slot = p5[b];

    // Stage p8 slice: p8[(a*B + b)*256 + c]
    #pragma unroll
    for (int i = t; i < A * 256; i += 256) {
        int a = i >> 8, c = i & 255;
        p8s[i] = p8[(a * B + b) * 256 + c];
    }
    if (t < 32) g[t] = g_row_scratch[b * D + d0 + t];

    float acc[A];
    #pragma unroll
    for (int a = 0; a < A; a++) acc[a] = 0.f;

    __syncthreads();

    const float* p1b = p1 + b * (S * D);
    const float* p7b = p7 + b * (S * D);
    float* out2b = out2 + b * (S * D);

    #pragma unroll 1
    for (int cb = 0; cb < 8; cb++) {
        // Fill: each thread handles 4 c values for its d lane.
        #pragma unroll
        for (int i = 0; i < 4; i++) {
            int c   = cb * 32 + ty * 4 + i;
            int idx = c * D + d0 + tx;                    // coalesced in tx
            float base = (c == slot) ? g[tx] : p1b[idx];
            float val  = fmaf(0.975f, p7b[idx], base);
            s[(ty * 4 + i) * 33 + tx] = val;
            #pragma unroll
            for (int a = 0; a < A; a++)
                acc[a] = fmaf(p8s[a * 256 + c], val, acc[a]);  // smem broadcast
        }
        __syncthreads();
        // Drain: out2[b, d0+r, cb*32+tx] = s[tx][r], coalesced in tx.
        #pragma unroll
        for (int i = 0; i < 4; i++) {
            int r = ty * 4 + i;
            out2b[(d0 + r) * D + cb * 32 + tx] = s[tx * 33 + r];
        }
        __syncthreads();
    }

    // Reduce acc across ty (8 partials per (a, d-lane)).
    #pragma unroll
    for (int a = 0; a < A; a++) red[(ty * A + a) * 32 + tx] = acc[a];
    __syncthreads();
    for (int j = t; j < A * 32; j += 256) {
        int a = j >> 5, dd = j & 31;
        float sum = 0.f;
        #pragma unroll
        for (int q = 0; q < 8; q++) sum += red[(q * A + a) * 32 + dd];
        out1[a * (B * D) + b * D + d0 + dd] = sum;
    }
}

extern "C" void kernel_launch(void* const* d_in, const int* in_sizes, int n_in,
                              void* d_out, int out_size) {
    const float* p1 = (const float*)d_in[0];
    const float* p2 = (const float*)d_in[1];
    const int*   p3 = (const int*)d_in[2];
    const int*   p4 = (const int*)d_in[3];
    const int*   p5 = (const int*)d_in[4];
    const int*   p6 = (const int*)d_in[5];
    const float* p7 = (const float*)d_in[6];
    const float* p8 = (const float*)d_in[7];

    float* out1 = (float*)d_out;                 // [12,6,256]
    float* out2 = out1 + A * B * D;              // [6,256,256]

    prep_kernel<<<B, 256>>>(p1, p2, p3, p4, p5, p6);
    dim3 grid(D / 32, B);
    fused_kernel<<<grid, 256>>>(p1, p7, p8, p5, out1, out2);
}

// round 3
// speedup vs baseline: 1.6272x; 1.6272x over previous
#include <cuda_runtime.h>

// Shapes (fixed):
//   p1: [6,256,256] f32   bank
//   p2: [131072,256] f32  table
//   p3: [6,1] i32         row ids into p2
//   p4: [1,256] i32       gather columns
//   p5: [6,1] i32         slot (c index) per batch
//   p6: [1,256] i32       scatter columns
//   p7: [6,256,256] f32   EMA state
//   p8: [12,6,256] f32    query features
// out1: [12,6,256] f32, out2: [6,256,256] f32 (concatenated in d_out)

#define B 6
#define S 256
#define D 256
#define A 12
#define CS 8            // c-splits (blocks along the reduction axis)
#define CLEN (S / CS)   // 32 c per block
#define ABD (A * B * D) // 18432

// Partial out1 sums, one slice per c-split. 8*12*6*256 floats = 576 KB.
__device__ float g_partial[CS * ABD];

// Fused kernel: grid = (D/32, B, CS). 256 threads: tx = d lane, ty = c subgroup.
// Each block handles a [32c x 32d] tile of `add` for one b:
//   add = (c==slot ? scattered row : p1) + 0.975*p7
//   out2[b,d,c] = add[b,c,d]                  (smem transpose)
//   partial[cs,a,b,d] = sum_{c in tile} p8[a,b,c]*add[b,c,d]
// The scattered row slice is reconstructed inline from p1/p2/p3/p4/p6.
__global__ __launch_bounds__(256)
void fused_kernel(const float* __restrict__ p1,
                  const float* __restrict__ p2,
                  const int* __restrict__ p3,
                  const int* __restrict__ p4,
                  const int* __restrict__ p5,
                  const int* __restrict__ p6,
                  const float* __restrict__ p7,
                  const float* __restrict__ p8,
                  float* __restrict__ out2) {
    __shared__ float p8s[A * CLEN];     // p8[a, b, c0:c0+32]
    __shared__ float s[32 * 33];        // transpose tile, padded
    __shared__ float g[32];             // scattered-row slice for this d tile
    __shared__ float red[8 * A * 32];   // cross-ty reduction

    const int d0 = blockIdx.x * 32;
    const int b  = blockIdx.y;
    const int cs = blockIdx.z;
    const int c0 = cs * CLEN;
    const int t  = threadIdx.x;
    const int tx = t & 31;
    const int ty = t >> 5;
    const int slot = p5[b];

    // Stage p8 slice for this c range.
    #pragma unroll
    for (int i = t; i < A * CLEN; i += 256) {
        int a = i / CLEN, cl = i % CLEN;
        p8s[i] = p8[(a * B + b) * 256 + c0 + cl];
    }

    // Scattered row slice: start from p1[b, slot, d0:d0+32], then apply
    // row[p6[j]] = p2[p3[b], p4[j]] for j hitting this d tile.
    if (t < 32) g[t] = p1[(b * S + slot) * D + d0 + t];
    __syncthreads();
    {
        int col = p6[t];
        if (col >= d0 && col < d0 + 32)
            g[col - d0] = p2[(long long)p3[b] * D + p4[t]];
    }
    __syncthreads();

    const float* p1b = p1 + b * (S * D);
    const float* p7b = p7 + b * (S * D);
    float* out2b = out2 + b * (S * D);

    float acc[A];
    #pragma unroll
    for (int a = 0; a < A; a++) acc[a] = 0.f;

    // Fill: each thread handles 4 c values for its d lane (coalesced in tx).
    #pragma unroll
    for (int i = 0; i < 4; i++) {
        int cl  = ty * 4 + i;
        int c   = c0 + cl;
        int idx = c * D + d0 + tx;
        float base = (c == slot) ? g[tx] : p1b[idx];
        float val  = fmaf(0.975f, p7b[idx], base);
        s[cl * 33 + tx] = val;
        #pragma unroll
        for (int a = 0; a < A; a++)
            acc[a] = fmaf(p8s[a * CLEN + cl], val, acc[a]);
    }
    __syncthreads();

    // Drain transpose: out2[b, d0+r, c0+tx], coalesced in tx.
    #pragma unroll
    for (int i = 0; i < 4; i++) {
        int r = ty * 4 + i;
        out2b[(d0 + r) * D + c0 + tx] = s[tx * 33 + r];
    }

    // Reduce acc across the 8 ty groups.
    #pragma unroll
    for (int a = 0; a < A; a++) red[(ty * A + a) * 32 + tx] = acc[a];
    __syncthreads();
    for (int j = t; j < A * 32; j += 256) {
        int a = j >> 5, dd = j & 31;
        float sum = 0.f;
        #pragma unroll
        for (int q = 0; q < 8; q++) sum += red[(q * A + a) * 32 + dd];
        g_partial[cs * ABD + (a * B + b) * D + d0 + dd] = sum;
    }
}

// Sum the CS partial slices into out1 with float4 loads/stores.
// ABD/4 = 4608 vec4 outputs -> 18 blocks of 256 threads.
__global__ __launch_bounds__(256)
void reduce_kernel(float* __restrict__ out1) {
    int v = blockIdx.x * 256 + threadIdx.x;      // vec4 index
    if (v < ABD / 4) {
        const float4* part = (const float4*)g_partial;
        float4 sum = part[v];
        #pragma unroll
        for (int cs = 1; cs < CS; cs++) {
            float4 p = part[cs * (ABD / 4) + v];
            sum.x += p.x; sum.y += p.y; sum.z += p.z; sum.w += p.w;
        }
        ((float4*)out1)[v] = sum;
    }
}

extern "C" void kernel_launch(void* const* d_in, const int* in_sizes, int n_in,
                              void* d_out, int out_size) {
    const float* p1 = (const float*)d_in[0];
    const float* p2 = (const float*)d_in[1];
    const int*   p3 = (const int*)d_in[2];
    const int*   p4 = (const int*)d_in[3];
    const int*   p5 = (const int*)d_in[4];
    const int*   p6 = (const int*)d_in[5];
    const float* p7 = (const float*)d_in[6];
    const float* p8 = (const float*)d_in[7];

    float* out1 = (float*)d_out;                 // [12,6,256]
    float* out2 = out1 + ABD;                    // [6,256,256]

    dim3 grid(D / 32, B, CS);
    fused_kernel<<<grid, 256>>>(p1, p2, p3, p4, p5, p6, p7, p8, out2);
    reduce_kernel<<<(ABD / 4 + 255) / 256, 256>>>(out1);
}